// round 15
// baseline (speedup 1.0000x reference)
#include <cuda_runtime.h>
#include <math.h>

#define NIMG 8
#define AA 3
#define HH 336
#define WW 336
#define HWSZ (HH*WW)            // 112896
#define MM (AA*HWSZ)            // 338688
#define PRE_K 2000
#define POST_N 1000
#define CAND_CAP 4096
#define MASK_ROWS 2048
#define MASK_WORDS 64
#define NEGV (-1e9f)
#define FULLM 0xffffffffu
#define GRID_FAT 1184           // 148 SMs * 8 blocks -> one wave at 256 thr

// ---------------- scratch (device globals; no allocations) ----------------
// Replay invariants: d_hist starts zero (.bss; re-zeroed by k4r each replay),
// d_validmask zeroed by k2 before k4r's atomicOr.
__device__ float              d_scores[NIMG * MM];                       // 10.8 MB (linear order)
__device__ unsigned int       d_hist[NIMG * 65536];                      // 2 MB
__device__ unsigned int       d_pref[NIMG * 65536];                      // 2 MB: #keys in bins > b
__device__ int                d_threshbin[NIMG];
__device__ int                d_candcount[NIMG];
__device__ unsigned long long d_cand[NIMG * CAND_CAP];                   // 256 KB (bin-grouped)
__device__ float4             d_boxes[NIMG * PRE_K];                     // 256 KB
__device__ float              d_selscore[NIMG * PRE_K];
__device__ float              d_area[NIMG * PRE_K];
__device__ unsigned int       d_maskbits[NIMG * MASK_ROWS * MASK_WORDS]; // 4 MB
__device__ unsigned int       d_validmask[NIMG * MASK_WORDS];

// ---------------- K1: sigmoid + store + ordered histogram (coalesced, 1 wave) ----------------
__global__ void k1_scores(const float* __restrict__ logits) {
    int stride = gridDim.x * blockDim.x;
    for (int t = blockIdx.x * blockDim.x + threadIdx.x; t < NIMG * MM; t += stride) {
        float x = logits[t];                 // linear = fully coalesced
        float s = 1.0f / (1.0f + expf(-x));
        d_scores[t] = s;                     // single source of truth for score bits
        int n = t / MM;
        unsigned u = __float_as_uint(s) | 0x80000000u;  // s >= 0 always
        atomicAdd(&d_hist[(n << 16) + (u >> 16)], 1u);
    }
}

// ---------------- K2: threshold bin + full suffix-prefix pref[] + cnt ----------------
__global__ void k2_thresh() {
    int n = blockIdx.x;
    int t = threadIdx.x;  // 256
    __shared__ unsigned csum[256];
    __shared__ unsigned ssuf[256];   // ssuf[c] = sum of csum[c'] for c' > c
    __shared__ unsigned bins[256];
    __shared__ int      s_chunk;
    __shared__ unsigned s_cum;
    const unsigned* h = d_hist + (n << 16);
    unsigned* pref = d_pref + (n << 16);
    int warp = t >> 5, lane = t & 31;
    for (int c = warp; c < 256; c += 8) {
        unsigned s = 0;
#pragma unroll
        for (int k = 0; k < 8; k++) s += h[c * 256 + k * 32 + lane];  // coalesced
#pragma unroll
        for (int o = 16; o; o >>= 1) s += __shfl_down_sync(FULLM, s, o);
        if (lane == 0) csum[c] = s;
    }
    __syncthreads();
    if (t == 0) {
        unsigned run = 0;
        for (int c = 255; c >= 0; c--) { ssuf[c] = run; run += csum[c]; }
        unsigned cum = 0;
        int chunk = 0;
        for (int c = 255; c >= 0; c--) {
            if (cum + csum[c] >= PRE_K) { chunk = c; break; }
            cum += csum[c];
        }
        s_chunk = chunk;
        s_cum = cum;
    }
    __syncthreads();
    // pref[bin] = #keys in bins strictly greater; coalesced warp suffix scans
    for (int c = warp; c < 256; c += 8) {
        unsigned run = ssuf[c];
        for (int k = 7; k >= 0; k--) {
            unsigned v = h[c * 256 + k * 32 + lane];          // coalesced
            unsigned x = v;                                   // inclusive suffix over lanes >= l
#pragma unroll
            for (int o = 1; o < 32; o <<= 1) {
                unsigned y = __shfl_down_sync(FULLM, x, o);
                if (lane + o < 32) x += y;
            }
            pref[c * 256 + k * 32 + lane] = run + x - v;      // strictly-greater count
            run += __shfl_sync(FULLM, x, 0);                  // total of this 32-group
        }
    }
    __syncthreads();
    int chunk = s_chunk;
    bins[t] = h[chunk * 256 + t];
    __syncthreads();
    if (t == 0) {
        unsigned cum = s_cum;
        int thresh = chunk * 256;
        for (int b = 255; b >= 0; b--) {
            cum += bins[b];
            if (cum >= PRE_K) { thresh = chunk * 256 + b; break; }
        }
        d_threshbin[n] = thresh;
        d_candcount[n] = (int)cum;       // total keys in bins >= thresh
    }
    if (t < MASK_WORDS) d_validmask[n * MASK_WORDS + t] = 0u;
}

// ---------------- K3: scatter candidates to bin-grouped slots ----------------
__global__ void k3_compact() {
    int stride = gridDim.x * blockDim.x;
    int t0 = blockIdx.x * blockDim.x + threadIdx.x;
    for (int t = t0; t < NIMG * MM; t += stride) {
        float s = d_scores[t];               // identical bits to k1 by construction
        int n = t / MM;
        int rem = t - n * MM;
        unsigned u = __float_as_uint(s) | 0x80000000u;
        int bin = (int)(u >> 16);
        if (bin >= d_threshbin[n]) {
            int a  = rem / HWSZ;
            int hw = rem - a * HWSZ;
            unsigned f = (unsigned)(hw * AA + a);   // score-order index
            unsigned old = atomicAdd(&d_hist[(n << 16) + bin], 0xFFFFFFFFu);  // -1; old >= 1
            unsigned slot = d_pref[(n << 16) + bin] + (old - 1u);
            if (slot < CAND_CAP) {
                d_cand[n * CAND_CAP + slot] =
                    ((unsigned long long)u << 32) | (unsigned long long)(0xFFFFFFFFu - f);
            }
        }
    }
    // NOTE: hist zeroing moved to k4r (k3 writes hist; zeroing here would race)
}

// ---------------- K4r: exact rank via bin-mate scan + fused decode ----------------
__global__ __launch_bounds__(128) void k4r_rankdecode(const float* __restrict__ anchors,
                                                      const float* __restrict__ breg) {
    int n = blockIdx.x >> 5;                 // 32 blocks per image
    int r = (blockIdx.x & 31) * 128 + threadIdx.x;   // 0..4095
    int cnt = d_candcount[n];
    if (cnt > CAND_CAP) cnt = CAND_CAP;
    const float XCLIP = 4.135166556742356f;  // log(1000/16)

    if (r < cnt) {
        unsigned long long key = d_cand[n * CAND_CAP + r];
        unsigned bin  = (unsigned)(key >> 48);
        unsigned base = d_pref[(n << 16) + bin];
        unsigned end  = (bin > 0) ? d_pref[(n << 16) + bin - 1] : (unsigned)cnt;
        if (end > (unsigned)cnt) end = (unsigned)cnt;
        unsigned rank = base;
        for (unsigned j = base; j < end; j++)
            rank += (d_cand[n * CAND_CAP + j] > key);   // keys unique -> rank unique
        if (rank < PRE_K) {
            unsigned ub = (unsigned)(key >> 32);
            unsigned sbits = (ub & 0x80000000u) ? (ub ^ 0x80000000u) : ~ub;
            float s = __uint_as_float(sbits);
            unsigned f = 0xFFFFFFFFu - (unsigned)(key & 0xFFFFFFFFull);
            int a  = (int)(f % AA);
            int hw = (int)(f / AA);
            float4 anc = ((const float4*)anchors)[(size_t)n * MM + f];
            const float* rp = breg + ((size_t)n * (AA * 4) + a * 4) * HWSZ + hw;
            float dx = rp[0];
            float dy = rp[HWSZ];
            float dwv = rp[2 * HWSZ];
            float dhv = rp[3 * HWSZ];
            float aw = __fadd_rn(__fsub_rn(anc.z, anc.x), 1.0f);
            float ah = __fadd_rn(__fsub_rn(anc.w, anc.y), 1.0f);
            float cx = __fadd_rn(anc.x, __fmul_rn(0.5f, aw));
            float cy = __fadd_rn(anc.y, __fmul_rn(0.5f, ah));
            dwv = fminf(dwv, XCLIP);
            dhv = fminf(dhv, XCLIP);
            float pcx = __fadd_rn(__fmul_rn(dx, aw), cx);
            float pcy = __fadd_rn(__fmul_rn(dy, ah), cy);
            float pw = __fmul_rn((float)exp((double)dwv), aw);
            float ph = __fmul_rn((float)exp((double)dhv), ah);
            float hpw = __fmul_rn(0.5f, pw);
            float hph = __fmul_rn(0.5f, ph);
            float x1 = __fsub_rn(pcx, hpw);
            float y1 = __fsub_rn(pcy, hph);
            float x2 = __fsub_rn(__fadd_rn(pcx, hpw), 1.0f);
            float y2 = __fsub_rn(__fadd_rn(pcy, hph), 1.0f);
            x1 = fminf(fmaxf(x1, 0.0f), 1332.0f);
            x2 = fminf(fmaxf(x2, 0.0f), 1332.0f);
            y1 = fminf(fmaxf(y1, 0.0f), 799.0f);
            y2 = fminf(fmaxf(y2, 0.0f), 799.0f);
            float ws = __fadd_rn(__fsub_rn(x2, x1), 1.0f);
            float hs = __fadd_rn(__fsub_rn(y2, y1), 1.0f);
            bool keepf = (ws >= 0.0f) && (hs >= 0.0f);
            d_boxes[n * PRE_K + rank] = make_float4(x1, y1, x2, y2);
            d_area[n * PRE_K + rank] = __fmul_rn(ws, hs);
            d_selscore[n * PRE_K + rank] = keepf ? s : NEGV;
            if (keepf)
                atomicOr(&d_validmask[n * MASK_WORDS + (rank >> 5)], 1u << (rank & 31));
        }
    }
    // re-zero hist for the next replay (bins >= thresh already 0 via k3 decrements)
    int g = blockIdx.x * 128 + threadIdx.x;
    int gs = gridDim.x * 128;
    for (int t = g; t < NIMG * 65536; t += gs) d_hist[t] = 0u;
}

// ---------------- K5: 2000x2000 suppression bitmask (reg rows, no div) ----------------
#define RPB 32
__global__ __launch_bounds__(128) void k5_mask() {
    __shared__ float4 sb[2048];
    __shared__ float  sa[2048];
    const int bpi = (PRE_K + RPB - 1) / RPB;  // 63
    int n  = blockIdx.x / bpi;
    int rb = (blockIdx.x % bpi) * RPB;
    int tid = threadIdx.x;  // 128
    for (int i = tid; i < 2048; i += 128) {
        if (i < PRE_K) { sb[i] = d_boxes[n * PRE_K + i]; sa[i] = d_area[n * PRE_K + i]; }
        else           { sb[i] = make_float4(0.f, 0.f, -1.f, -1.f); sa[i] = 1.0f; }
    }
    __syncthreads();
    int warp = tid >> 5, lane = tid & 31;
    int r0 = rb + warp * 8;
    if (r0 >= PRE_K) return;   // whole-warp tail (no further block sync)

    float4 bi[8]; float ai[8];
#pragma unroll
    for (int d = 0; d < 8; d++) { bi[d] = sb[r0 + d]; ai[d] = sa[r0 + d]; }
    unsigned* rowbase = d_maskbits + ((size_t)n * MASK_ROWS + r0) * MASK_WORDS;

    // iou > 0.7  <=>  inter > (0.7/1.7)*(ai+aj)   (areas >= 0 => denom > 0)
    // guard band +-~0.06%; ambiguous pairs fall back to the exact division.
    const float HIC = 0.41200f, LOC = 0.41153f;
    for (int w = 0; w < 64; w++) {
        int j = (w << 5) + lane;
        float4 bj = sb[j];
        float  aj = sa[j];
        unsigned words[8];
#pragma unroll
        for (int d = 0; d < 8; d++) {
            float xx1 = fmaxf(bi[d].x, bj.x);
            float yy1 = fmaxf(bi[d].y, bj.y);
            float xx2 = fminf(bi[d].z, bj.z);
            float yy2 = fminf(bi[d].w, bj.w);
            float iw = fmaxf(__fadd_rn(__fsub_rn(xx2, xx1), 1.0f), 0.0f);
            float ih = fmaxf(__fadd_rn(__fsub_rn(yy2, yy1), 1.0f), 0.0f);
            float inter = __fmul_rn(iw, ih);
            float ssum  = __fadd_rn(ai[d], aj);
            bool sup;
            if (inter > __fmul_rn(HIC, ssum))      sup = true;
            else if (inter < __fmul_rn(LOC, ssum)) sup = false;
            else sup = __fdiv_rn(inter, __fsub_rn(ssum, inter)) > 0.7f;
            words[d] = __ballot_sync(FULLM, sup);
        }
        if (lane == 0) {
#pragma unroll
            for (int d = 0; d < 8; d++) rowbase[(size_t)d * MASK_WORDS + w] = words[d];
        }
    }
}

// ---------------- K6: serial greedy NMS scan, 1 warp per image ----------------
__device__ __forceinline__ void k6_load_group(const unsigned* __restrict__ maskb, int lane,
                                              int i0, unsigned (&b0)[8], unsigned (&b1)[8]) {
#pragma unroll
    for (int d = 0; d < 8; d++) {
        const unsigned* r = maskb + (size_t)(i0 + d) * MASK_WORDS;
        b0[d] = r[lane];
        b1[d] = r[lane + 32];
    }
}

__device__ __forceinline__ void k6_proc_group(int i0, int lane,
                                              unsigned (&b0)[8], unsigned (&b1)[8],
                                              unsigned& sup0, unsigned& sup1,
                                              unsigned val0, unsigned val1,
                                              int& count, int* list) {
    int Wd = i0 >> 5;             // constant across the 8-row group
    int slot = Wd >> 5;
    int ol = Wd & 31;
    unsigned kb = slot ? sup1 : sup0;
    unsigned kv = slot ? val1 : val0;
    unsigned keep8 = 0;
    int bit0 = i0 & 31;
#pragma unroll
    for (int d = 0; d < 8; d++) {
        unsigned m = 1u << (bit0 + d);
        if ((kv & m) && !(kb & m)) {
            keep8 |= (1u << d);
            kb |= slot ? b1[d] : b0[d];   // owner lane holds word Wd of row i0+d
        }
    }
    keep8 = __shfl_sync(FULLM, keep8, ol);
#pragma unroll
    for (int d = 0; d < 8; d++) {
        if (keep8 & (1u << d)) { sup0 |= b0[d]; sup1 |= b1[d]; }
    }
    if (lane == 0) {
        int c = count;
#pragma unroll
        for (int d = 0; d < 8; d++) {
            if (keep8 & (1u << d)) {
                if (c < POST_N) list[c] = i0 + d;
                c++;
            }
        }
    }
    count += __popc(keep8);
}

__global__ __launch_bounds__(32) void k6_nms(float* __restrict__ out) {
    int n = blockIdx.x;
    int lane = threadIdx.x;
    __shared__ int list[POST_N];
    const unsigned* maskb = d_maskbits + (size_t)n * MASK_ROWS * MASK_WORDS;
    unsigned sup0 = 0, sup1 = 0;
    unsigned val0 = d_validmask[n * MASK_WORDS + lane];
    unsigned val1 = d_validmask[n * MASK_WORDS + 32 + lane];
    int count = 0;
    unsigned A0[8], A1[8], B0[8], B1[8];

    k6_load_group(maskb, lane, 0, A0, A1);
    int i0 = 0;
    while (true) {
        k6_load_group(maskb, lane, i0 + 8, B0, B1);   // prefetch (rows < 2048, padded)
        k6_proc_group(i0, lane, A0, A1, sup0, sup1, val0, val1, count, list);
        i0 += 8;
        if (count >= POST_N || i0 >= PRE_K) break;
        k6_load_group(maskb, lane, i0 + 8, A0, A1);
        k6_proc_group(i0, lane, B0, B1, sup0, sup1, val0, val1, count, list);
        i0 += 8;
        if (count >= POST_N || i0 >= PRE_K) break;
    }
    __syncwarp();

    float* o = out + (size_t)n * POST_N * 5;
    int cmax = count < POST_N ? count : POST_N;
    for (int r = lane; r < POST_N; r += 32) {
        float v0 = 0.f, v1 = 0.f, v2 = 0.f, v3 = 0.f, v4 = 0.f;
        if (r < cmax) {
            int i = list[r];
            float4 b = d_boxes[n * PRE_K + i];
            v0 = b.x; v1 = b.y; v2 = b.z; v3 = b.w;
            v4 = d_selscore[n * PRE_K + i];
        }
        o[r * 5 + 0] = v0;
        o[r * 5 + 1] = v1;
        o[r * 5 + 2] = v2;
        o[r * 5 + 3] = v3;
        o[r * 5 + 4] = v4;
    }
}

// ---------------- launch ----------------
extern "C" void kernel_launch(void* const* d_in, const int* in_sizes, int n_in,
                              void* d_out, int out_size) {
    const float* anchors = (const float*)d_in[0];   // [8, 338688, 4]
    const float* logits  = (const float*)d_in[1];   // [8, 3, 336, 336]
    const float* breg    = (const float*)d_in[2];   // [8, 12, 336, 336]
    float* out = (float*)d_out;                     // [8, 1000, 5]

    (void)in_sizes; (void)n_in; (void)out_size;

    k1_scores<<<GRID_FAT, 256>>>(logits);
    k2_thresh<<<NIMG, 256>>>();
    k3_compact<<<GRID_FAT, 256>>>();
    k4r_rankdecode<<<NIMG * 32, 128>>>(anchors, breg);
    k5_mask<<<NIMG * ((PRE_K + RPB - 1) / RPB), 128>>>();
    k6_nms<<<NIMG, 32>>>(out);
}

// round 17
// speedup vs baseline: 1.0161x; 1.0161x over previous
#include <cuda_runtime.h>
#include <math.h>

#define NIMG 8
#define AA 3
#define HH 336
#define WW 336
#define HWSZ (HH*WW)            // 112896
#define MM (AA*HWSZ)            // 338688
#define PRE_K 2000
#define POST_N 1000
#define CAND_CAP 4096
#define MASK_ROWS 2048
#define MASK_WORDS 64
#define NEGV (-1e9f)
#define FULLM 0xffffffffu
#define GRID_FAT 1184           // 148 SMs * 8 blocks -> one wave at 256 thr

// ---------------- scratch (device globals; no allocations) ----------------
// Replay invariants: d_hist starts zero (.bss; re-zeroed by k4r each replay),
// d_validmask zeroed by k2 before k4r's atomicOr.
__device__ float              d_scores[NIMG * MM];                       // 10.8 MB (linear order)
__device__ unsigned int       d_hist[NIMG * 65536];                      // 2 MB
__device__ unsigned int       d_pref[NIMG * 65536];                      // 2 MB: #keys in bins > b
__device__ int                d_threshbin[NIMG];
__device__ int                d_candcount[NIMG];
__device__ unsigned long long d_cand[NIMG * CAND_CAP];                   // 256 KB (bin-grouped)
__device__ float4             d_boxes[NIMG * PRE_K];                     // 256 KB
__device__ float              d_selscore[NIMG * PRE_K];
__device__ float              d_area[NIMG * PRE_K];
__device__ unsigned int       d_maskbits[NIMG * MASK_ROWS * MASK_WORDS]; // 4 MB
__device__ unsigned int       d_validmask[NIMG * MASK_WORDS];

// ---------------- K1: sigmoid + store + ordered histogram (coalesced, 1 wave) ----------------
__global__ void k1_scores(const float* __restrict__ logits) {
    int stride = gridDim.x * blockDim.x;
    for (int t = blockIdx.x * blockDim.x + threadIdx.x; t < NIMG * MM; t += stride) {
        float x = logits[t];                 // linear = fully coalesced
        float s = 1.0f / (1.0f + expf(-x));
        d_scores[t] = s;                     // single source of truth for score bits
        int n = t / MM;
        unsigned u = __float_as_uint(s) | 0x80000000u;  // s >= 0 always
        atomicAdd(&d_hist[(n << 16) + (u >> 16)], 1u);
    }
}

// ---------------- K2: hierarchical suffix scan -> pref[] + threshold (parallel) ----------------
__global__ void k2_thresh() {
    int n = blockIdx.x;
    int t = threadIdx.x;  // 256
    int warp = t >> 5, lane = t & 31;
    __shared__ unsigned csum[256];
    __shared__ unsigned ssuf[256];       // suffix over chunks (inclusive -> exclusive)
    __shared__ unsigned gs[256][9];      // [chunk][group] sums, padded vs bank conflicts
    const unsigned* h = d_hist + (n << 16);
    unsigned* pref = d_pref + (n << 16);

    // level 1: per-group (32-bin) sums + per-chunk (256-bin) sums; coalesced, independent
    for (int c = warp; c < 256; c += 8) {
        unsigned tot = 0;
#pragma unroll
        for (int k = 0; k < 8; k++) {
            unsigned v = h[c * 256 + k * 32 + lane];
            tot += v;
            unsigned g = v;
#pragma unroll
            for (int o = 16; o; o >>= 1) g += __shfl_down_sync(FULLM, g, o);
            if (lane == 0) gs[c][k] = g;
        }
#pragma unroll
        for (int o = 16; o; o >>= 1) tot += __shfl_down_sync(FULLM, tot, o);
        if (lane == 0) csum[c] = tot;
    }
    __syncthreads();

    // level 2: inclusive suffix scan over 256 chunk sums (Hillis-Steele), then exclusive
    unsigned mine = csum[t];
    ssuf[t] = mine;
    __syncthreads();
    for (int o = 1; o < 256; o <<= 1) {
        unsigned v = (t + o < 256) ? ssuf[t + o] : 0u;
        __syncthreads();
        ssuf[t] += v;
        __syncthreads();
    }
    unsigned excl = ssuf[t] - mine;      // keys in chunks strictly above chunk t
    __syncthreads();
    ssuf[t] = excl;
    __syncthreads();

    // level 3: per-chunk suffix over its 8 group sums (thread t owns chunk t)
    {
        unsigned run = ssuf[t];
        unsigned r[8];
#pragma unroll
        for (int k = 7; k >= 0; k--) { r[k] = run; run += gs[t][k]; }
#pragma unroll
        for (int k = 0; k < 8; k++) gs[t][k] = r[k];   // now: keys in bins above group k
    }
    __syncthreads();

    // level 4: per-bin pref via independent intra-group lane suffixes + threshold detect
    for (int c = warp; c < 256; c += 8) {
#pragma unroll
        for (int k = 0; k < 8; k++) {
            int b = c * 256 + k * 32 + lane;
            unsigned v = h[b];
            unsigned x = v;                              // inclusive suffix over lanes >= l
#pragma unroll
            for (int o = 1; o < 32; o <<= 1) {
                unsigned y = __shfl_down_sync(FULLM, x, o);
                if (lane + o < 32) x += y;
            }
            unsigned p = gs[c][k] + (x - v);             // keys in bins strictly > b
            pref[b] = p;
            if (p < PRE_K && p + v >= PRE_K) {           // unique crossing bin
                d_threshbin[n] = b;
                d_candcount[n] = (int)(p + v);
            }
        }
    }
    if (t < MASK_WORDS) d_validmask[n * MASK_WORDS + t] = 0u;
}

// ---------------- K3: scatter candidates to bin-grouped slots ----------------
__global__ void k3_compact() {
    int stride = gridDim.x * blockDim.x;
    int t0 = blockIdx.x * blockDim.x + threadIdx.x;
    for (int t = t0; t < NIMG * MM; t += stride) {
        float s = d_scores[t];               // identical bits to k1 by construction
        int n = t / MM;
        int rem = t - n * MM;
        unsigned u = __float_as_uint(s) | 0x80000000u;
        int bin = (int)(u >> 16);
        if (bin >= d_threshbin[n]) {
            int a  = rem / HWSZ;
            int hw = rem - a * HWSZ;
            unsigned f = (unsigned)(hw * AA + a);   // score-order index
            unsigned old = atomicAdd(&d_hist[(n << 16) + bin], 0xFFFFFFFFu);  // -1; old >= 1
            unsigned slot = d_pref[(n << 16) + bin] + (old - 1u);
            if (slot < CAND_CAP) {
                d_cand[n * CAND_CAP + slot] =
                    ((unsigned long long)u << 32) | (unsigned long long)(0xFFFFFFFFu - f);
            }
        }
    }
    // NOTE: hist zeroing lives in k4r (k3 writes hist; zeroing here would race)
}

// ---------------- K4r: exact rank via bin-mate scan + fused decode ----------------
__global__ __launch_bounds__(128) void k4r_rankdecode(const float* __restrict__ anchors,
                                                      const float* __restrict__ breg) {
    int n = blockIdx.x >> 5;                 // 32 blocks per image
    int r = (blockIdx.x & 31) * 128 + threadIdx.x;   // 0..4095
    int cnt = d_candcount[n];
    if (cnt > CAND_CAP) cnt = CAND_CAP;
    const float XCLIP = 4.135166556742356f;  // log(1000/16)

    if (r < cnt) {
        unsigned long long key = d_cand[n * CAND_CAP + r];
        unsigned bin  = (unsigned)(key >> 48);
        unsigned base = d_pref[(n << 16) + bin];
        unsigned end  = (bin > 0) ? d_pref[(n << 16) + bin - 1] : (unsigned)cnt;
        if (end > (unsigned)cnt) end = (unsigned)cnt;
        unsigned rank = base;
        for (unsigned j = base; j < end; j++)
            rank += (d_cand[n * CAND_CAP + j] > key);   // keys unique -> rank unique
        if (rank < PRE_K) {
            unsigned ub = (unsigned)(key >> 32);
            unsigned sbits = (ub & 0x80000000u) ? (ub ^ 0x80000000u) : ~ub;
            float s = __uint_as_float(sbits);
            unsigned f = 0xFFFFFFFFu - (unsigned)(key & 0xFFFFFFFFull);
            int a  = (int)(f % AA);
            int hw = (int)(f / AA);
            float4 anc = ((const float4*)anchors)[(size_t)n * MM + f];
            const float* rp = breg + ((size_t)n * (AA * 4) + a * 4) * HWSZ + hw;
            float dx = rp[0];
            float dy = rp[HWSZ];
            float dwv = rp[2 * HWSZ];
            float dhv = rp[3 * HWSZ];
            float aw = __fadd_rn(__fsub_rn(anc.z, anc.x), 1.0f);
            float ah = __fadd_rn(__fsub_rn(anc.w, anc.y), 1.0f);
            float cx = __fadd_rn(anc.x, __fmul_rn(0.5f, aw));
            float cy = __fadd_rn(anc.y, __fmul_rn(0.5f, ah));
            dwv = fminf(dwv, XCLIP);
            dhv = fminf(dhv, XCLIP);
            float pcx = __fadd_rn(__fmul_rn(dx, aw), cx);
            float pcy = __fadd_rn(__fmul_rn(dy, ah), cy);
            float pw = __fmul_rn((float)exp((double)dwv), aw);
            float ph = __fmul_rn((float)exp((double)dhv), ah);
            float hpw = __fmul_rn(0.5f, pw);
            float hph = __fmul_rn(0.5f, ph);
            float x1 = __fsub_rn(pcx, hpw);
            float y1 = __fsub_rn(pcy, hph);
            float x2 = __fsub_rn(__fadd_rn(pcx, hpw), 1.0f);
            float y2 = __fsub_rn(__fadd_rn(pcy, hph), 1.0f);
            x1 = fminf(fmaxf(x1, 0.0f), 1332.0f);
            x2 = fminf(fmaxf(x2, 0.0f), 1332.0f);
            y1 = fminf(fmaxf(y1, 0.0f), 799.0f);
            y2 = fminf(fmaxf(y2, 0.0f), 799.0f);
            float ws = __fadd_rn(__fsub_rn(x2, x1), 1.0f);
            float hs = __fadd_rn(__fsub_rn(y2, y1), 1.0f);
            bool keepf = (ws >= 0.0f) && (hs >= 0.0f);
            d_boxes[n * PRE_K + rank] = make_float4(x1, y1, x2, y2);
            d_area[n * PRE_K + rank] = __fmul_rn(ws, hs);
            d_selscore[n * PRE_K + rank] = keepf ? s : NEGV;
            if (keepf)
                atomicOr(&d_validmask[n * MASK_WORDS + (rank >> 5)], 1u << (rank & 31));
        }
    }
    // re-zero hist for the next replay (bins >= thresh already 0 via k3 decrements)
    int g = blockIdx.x * 128 + threadIdx.x;
    int gs2 = gridDim.x * 128;
    for (int t = g; t < NIMG * 65536; t += gs2) d_hist[t] = 0u;
}

// ---------------- K5: 2000x2000 suppression bitmask (reg rows, no div) ----------------
#define RPB 32
__global__ __launch_bounds__(128) void k5_mask() {
    __shared__ float4 sb[2048];
    __shared__ float  sa[2048];
    const int bpi = (PRE_K + RPB - 1) / RPB;  // 63
    int n  = blockIdx.x / bpi;
    int rb = (blockIdx.x % bpi) * RPB;
    int tid = threadIdx.x;  // 128
    for (int i = tid; i < 2048; i += 128) {
        if (i < PRE_K) { sb[i] = d_boxes[n * PRE_K + i]; sa[i] = d_area[n * PRE_K + i]; }
        else           { sb[i] = make_float4(0.f, 0.f, -1.f, -1.f); sa[i] = 1.0f; }
    }
    __syncthreads();
    int warp = tid >> 5, lane = tid & 31;
    int r0 = rb + warp * 8;
    if (r0 >= PRE_K) return;   // whole-warp tail (no further block sync)

    float4 bi[8]; float ai[8];
#pragma unroll
    for (int d = 0; d < 8; d++) { bi[d] = sb[r0 + d]; ai[d] = sa[r0 + d]; }
    unsigned* rowbase = d_maskbits + ((size_t)n * MASK_ROWS + r0) * MASK_WORDS;

    // iou > 0.7  <=>  inter > (0.7/1.7)*(ai+aj)   (areas >= 0 => denom > 0)
    // guard band +-~0.06%; ambiguous pairs fall back to the exact division.
    const float HIC = 0.41200f, LOC = 0.41153f;
    for (int w = 0; w < 64; w++) {
        int j = (w << 5) + lane;
        float4 bj = sb[j];
        float  aj = sa[j];
        unsigned words[8];
#pragma unroll
        for (int d = 0; d < 8; d++) {
            float xx1 = fmaxf(bi[d].x, bj.x);
            float yy1 = fmaxf(bi[d].y, bj.y);
            float xx2 = fminf(bi[d].z, bj.z);
            float yy2 = fminf(bi[d].w, bj.w);
            float iw = fmaxf(__fadd_rn(__fsub_rn(xx2, xx1), 1.0f), 0.0f);
            float ih = fmaxf(__fadd_rn(__fsub_rn(yy2, yy1), 1.0f), 0.0f);
            float inter = __fmul_rn(iw, ih);
            float ssum  = __fadd_rn(ai[d], aj);
            bool sup;
            if (inter > __fmul_rn(HIC, ssum))      sup = true;
            else if (inter < __fmul_rn(LOC, ssum)) sup = false;
            else sup = __fdiv_rn(inter, __fsub_rn(ssum, inter)) > 0.7f;
            words[d] = __ballot_sync(FULLM, sup);
        }
        if (lane == 0) {
#pragma unroll
            for (int d = 0; d < 8; d++) rowbase[(size_t)d * MASK_WORDS + w] = words[d];
        }
    }
}

// ---------------- K6: serial greedy NMS scan, 1 warp per image ----------------
__device__ __forceinline__ void k6_load_group(const unsigned* __restrict__ maskb, int lane,
                                              int i0, unsigned (&b0)[8], unsigned (&b1)[8]) {
#pragma unroll
    for (int d = 0; d < 8; d++) {
        const unsigned* r = maskb + (size_t)(i0 + d) * MASK_WORDS;
        b0[d] = r[lane];
        b1[d] = r[lane + 32];
    }
}

__device__ __forceinline__ void k6_proc_group(int i0, int lane,
                                              unsigned (&b0)[8], unsigned (&b1)[8],
                                              unsigned& sup0, unsigned& sup1,
                                              unsigned val0, unsigned val1,
                                              int& count, int* list) {
    int Wd = i0 >> 5;             // constant across the 8-row group
    int slot = Wd >> 5;
    int ol = Wd & 31;
    unsigned kb = slot ? sup1 : sup0;
    unsigned kv = slot ? val1 : val0;
    unsigned keep8 = 0;
    int bit0 = i0 & 31;
#pragma unroll
    for (int d = 0; d < 8; d++) {
        unsigned m = 1u << (bit0 + d);
        if ((kv & m) && !(kb & m)) {
            keep8 |= (1u << d);
            kb |= slot ? b1[d] : b0[d];   // owner lane holds word Wd of row i0+d
        }
    }
    keep8 = __shfl_sync(FULLM, keep8, ol);
#pragma unroll
    for (int d = 0; d < 8; d++) {
        if (keep8 & (1u << d)) { sup0 |= b0[d]; sup1 |= b1[d]; }
    }
    if (lane == 0) {
        int c = count;
#pragma unroll
        for (int d = 0; d < 8; d++) {
            if (keep8 & (1u << d)) {
                if (c < POST_N) list[c] = i0 + d;
                c++;
            }
        }
    }
    count += __popc(keep8);
}

__global__ __launch_bounds__(32) void k6_nms(float* __restrict__ out) {
    int n = blockIdx.x;
    int lane = threadIdx.x;
    __shared__ int list[POST_N];
    const unsigned* maskb = d_maskbits + (size_t)n * MASK_ROWS * MASK_WORDS;
    unsigned sup0 = 0, sup1 = 0;
    unsigned val0 = d_validmask[n * MASK_WORDS + lane];
    unsigned val1 = d_validmask[n * MASK_WORDS + 32 + lane];
    int count = 0;
    unsigned A0[8], A1[8], B0[8], B1[8];

    k6_load_group(maskb, lane, 0, A0, A1);
    int i0 = 0;
    while (true) {
        k6_load_group(maskb, lane, i0 + 8, B0, B1);   // prefetch (rows < 2048, padded)
        k6_proc_group(i0, lane, A0, A1, sup0, sup1, val0, val1, count, list);
        i0 += 8;
        if (count >= POST_N || i0 >= PRE_K) break;
        k6_load_group(maskb, lane, i0 + 8, A0, A1);
        k6_proc_group(i0, lane, B0, B1, sup0, sup1, val0, val1, count, list);
        i0 += 8;
        if (count >= POST_N || i0 >= PRE_K) break;
    }
    __syncwarp();

    float* o = out + (size_t)n * POST_N * 5;
    int cmax = count < POST_N ? count : POST_N;
    for (int r = lane; r < POST_N; r += 32) {
        float v0 = 0.f, v1 = 0.f, v2 = 0.f, v3 = 0.f, v4 = 0.f;
        if (r < cmax) {
            int i = list[r];
            float4 b = d_boxes[n * PRE_K + i];
            v0 = b.x; v1 = b.y; v2 = b.z; v3 = b.w;
            v4 = d_selscore[n * PRE_K + i];
        }
        o[r * 5 + 0] = v0;
        o[r * 5 + 1] = v1;
        o[r * 5 + 2] = v2;
        o[r * 5 + 3] = v3;
        o[r * 5 + 4] = v4;
    }
}

// ---------------- launch ----------------
extern "C" void kernel_launch(void* const* d_in, const int* in_sizes, int n_in,
                              void* d_out, int out_size) {
    const float* anchors = (const float*)d_in[0];   // [8, 338688, 4]
    const float* logits  = (const float*)d_in[1];   // [8, 3, 336, 336]
    const float* breg    = (const float*)d_in[2];   // [8, 12, 336, 336]
    float* out = (float*)d_out;                     // [8, 1000, 5]

    (void)in_sizes; (void)n_in; (void)out_size;

    k1_scores<<<GRID_FAT, 256>>>(logits);
    k2_thresh<<<NIMG, 256>>>();
    k3_compact<<<GRID_FAT, 256>>>();
    k4r_rankdecode<<<NIMG * 32, 128>>>(anchors, breg);
    k5_mask<<<NIMG * ((PRE_K + RPB - 1) / RPB), 128>>>();
    k6_nms<<<NIMG, 32>>>(out);
}